// round 17
// baseline (speedup 1.0000x reference)
#include <cuda_runtime.h>
#include <cuda_bf16.h>

// NeighborSearch_batch via 33x33 uniform grid — R16 (measured 36.4us) with
// query binning split 2-ways by query index: each half is cell-sorted into
// its own dense region; halves are back-to-back so the query kernel is
// UNCHANGED. B=8, n=9225, m=4096, d=2, r=0.03.
// Output (float32): neighbors_index [B,m,64] then row_splits [B,m+1].

#define BATCH  8
#define NPTS   9225
#define NQ     4096
#define MAXN   64
#define GRID   33
#define NCELLS (GRID * GRID)      // 1089
#define CAP    64                 // per-query accept cap (observed max ~50)

#define DSPLIT 3                  // data thirds per batch (by gy)
#define GYS    11                 // rows per data third
#define NCOWN  (GYS * GRID)       // 363 cells per third
#define CAPH   4096               // per-third point capacity (mean 3075)
#define QSPLIT 2                  // query halves per batch (by query index)
#define QHALF  (NQ / QSPLIT)      // 2048
#define PER_B  (DSPLIT + QSPLIT)  // 5 CTAs per batch in bin_kernel

#define LPQ    4                  // lanes per query
#define QPB    32                 // queries per CTA
#define QTPB   (LPQ * QPB)        // 128 threads

__device__ int    g_cnt_cell[BATCH * NCELLS];
__device__ int    g_start   [BATCH * NCELLS];
__device__ float4 g_pts     [BATCH * DSPLIT * CAPH]; // per-third dense regions
__device__ float4 g_qpts    [BATCH * NQ];            // two dense halves, cell-sorted
__device__ int    g_counts  [BATCH * NQ];

__device__ __forceinline__ int cell_of(float x, float y) {
    int cx = (int)(x * (float)GRID); if (cx > GRID - 1) cx = GRID - 1; if (cx < 0) cx = 0;
    int cy = (int)(y * (float)GRID); if (cy > GRID - 1) cy = GRID - 1; if (cy < 0) cy = 0;
    return cy * GRID + cx;
}

// 40 CTAs: batch b = blockIdx.x/5; part 0..2 = data third (by cell row),
// part 3..4 = query half (by query index). One atomic pass (rank saved),
// scan, then place (no atomics).
__global__ void __launch_bounds__(1024)
bin_kernel(const float* __restrict__ data,
           const float* __restrict__ queries)
{
    __shared__ int scnt  [NCELLS];
    __shared__ int sstart[NCELLS];
    __shared__ int warp_sums[32];

    const int b    = blockIdx.x / PER_B;
    const int part = blockIdx.x - b * PER_B;
    const bool isq = (part >= DSPLIT);
    const int h    = part - DSPLIT;               // query half id (if isq)

    const int cbase = isq ? 0 : part * NCOWN;     // contiguous cell range
    const int nown  = isq ? NCELLS : NCOWN;
    const float2* src = isq
        ? ((const float2*)queries + (size_t)b * NQ + (size_t)h * QHALF)
        : ((const float2*)data    + (size_t)b * NPTS);

    const int t = threadIdx.x;
    const int lane = t & 31, wid = t >> 5;

    for (int i = t; i < nown; i += 1024) scnt[i] = 0;
    __syncthreads();

    // ---- pass 1: count (one atomic per owned point; rank saved) ----
    int pos[10];
    int rel[10];
    if (isq) {
        #pragma unroll
        for (int it = 0; it < 2; ++it) {          // 2048 queries / 1024 thr
            const int i = t + it * 1024;
            rel[it] = cell_of(src[i].x, src[i].y);
            pos[it] = atomicAdd(&scnt[rel[it]], 1);
        }
    } else {
        #pragma unroll
        for (int it = 0; it < 10; ++it) {
            const int i = t + it * 1024;
            rel[it] = -1;
            if (i < NPTS) {
                const float2 p = src[i];
                const int rc = cell_of(p.x, p.y) - cbase;
                if (rc >= 0 && rc < NCOWN) {
                    rel[it] = rc;
                    pos[it] = atomicAdd(&scnt[rc], 1);
                }
            }
        }
    }
    __syncthreads();

    // ---- exclusive scan over nown counts (2 elems/thread) ----
    const int i0 = 2 * t, i1 = 2 * t + 1;
    const int c0 = (i0 < nown) ? scnt[i0] : 0;
    const int c1 = (i1 < nown) ? scnt[i1] : 0;
    const int total = c0 + c1;

    int x = total;
    #pragma unroll
    for (int o = 1; o < 32; o <<= 1) {
        int y = __shfl_up_sync(0xFFFFFFFFu, x, o);
        if (lane >= o) x += y;
    }
    if (lane == 31) warp_sums[wid] = x;
    __syncthreads();
    if (wid == 0) {
        int w = warp_sums[lane];
        #pragma unroll
        for (int o = 1; o < 32; o <<= 1) {
            int y = __shfl_up_sync(0xFFFFFFFFu, w, o);
            if (lane >= o) w += y;
        }
        warp_sums[lane] = w;
    }
    __syncthreads();

    const int excl = (x - total) + (wid > 0 ? warp_sums[wid - 1] : 0);
    if (i0 < nown) {
        sstart[i0] = excl;
        if (!isq) {
            g_start[b * NCELLS + cbase + i0]    = excl + part * CAPH;
            g_cnt_cell[b * NCELLS + cbase + i0] = c0;
        }
    }
    if (i1 < nown) {
        sstart[i1] = excl + c0;
        if (!isq) {
            g_start[b * NCELLS + cbase + i1]    = excl + c0 + part * CAPH;
            g_cnt_cell[b * NCELLS + cbase + i1] = c1;
        }
    }
    __syncthreads();

    // ---- pass 2: place points (no atomics; reload via L1) ----
    // nn = RN(RN(x*x) + RN(y*y))  (matches jnp.sum(v*v, axis=-1))
    if (isq) {
        float4* dst = g_qpts + (size_t)b * NQ + (size_t)h * QHALF;
        #pragma unroll
        for (int it = 0; it < 2; ++it) {
            const int i = t + it * 1024;
            const float2 p = src[i];
            const float nn = __fadd_rn(__fmul_rn(p.x, p.x), __fmul_rn(p.y, p.y));
            dst[sstart[rel[it]] + pos[it]] =
                make_float4(p.x, p.y, nn, __int_as_float(h * QHALF + i));
        }
    } else {
        float4* dst = g_pts + (size_t)(b * DSPLIT + part) * CAPH;
        #pragma unroll
        for (int it = 0; it < 10; ++it) {
            if (rel[it] >= 0) {
                const int i = t + it * 1024;
                const float2 p = src[i];
                const float nn = __fadd_rn(__fmul_rn(p.x, p.x), __fmul_rn(p.y, p.y));
                dst[sstart[rel[it]] + pos[it]] =
                    make_float4(p.x, p.y, nn, __int_as_float(i));
            }
        }
    }
}

// ---- query kernel (R6/R16 verbatim) ----
__global__ void __launch_bounds__(QTPB)
query_kernel(const float* __restrict__ radius,
             float* __restrict__ nbr_idx)
{
    __shared__ int cand[CAP][QPB + 1];   // stride 33: conflict-free

    const int tid   = threadIdx.x;
    const int sub   = tid & (LPQ - 1);        // 0..3 within group
    const int qslot = tid >> 2;               // 0..31 query slot in CTA
    const int shift = (tid & 31) & ~(LPQ - 1);
    const unsigned gmask = 0xFu << shift;

    const int b = blockIdx.y;
    const int qbin = blockIdx.x * QPB + qslot;

    const float4 qv = g_qpts[(size_t)b * NQ + qbin];  // 4-lane broadcast
    const float q0 = qv.x;
    const float q1 = qv.y;
    const float qn = qv.z;
    const int   oq = __float_as_int(qv.w);

    const float r  = radius[0];
    const float r2 = __fmul_rn(r, r);
    int reach = (int)ceilf(r * (float)GRID);
    if (reach < 1) reach = 1;

    int cx = (int)(q0 * (float)GRID); if (cx > GRID - 1) cx = GRID - 1; if (cx < 0) cx = 0;
    int cy = (int)(q1 * (float)GRID); if (cy > GRID - 1) cy = GRID - 1; if (cy < 0) cy = 0;
    const int x0 = max(0, cx - reach), x1 = min(GRID - 1, cx + reach);
    const int y0 = max(0, cy - reach), y1 = min(GRID - 1, cy + reach);

    const float4* pts = g_pts + (size_t)b * DSPLIT * CAPH;
    const int* starts = g_start    + b * NCELLS;
    const int* cnts   = g_cnt_cell + b * NCELLS;

    int cnt = 0;

    for (int gy = y0; gy <= y1; ++gy) {
        const int ca = gy * GRID + x0;
        const int cb = gy * GRID + x1;
        const int s = starts[ca];
        const int e = starts[cb] + cnts[cb];
        // group-uniform trip count; lanes take i = ib+sub (coalesced 64B)
        for (int ib = s; ib < e; ib += LPQ) {
            const int i = ib + sub;
            bool acc = false;
            int idx = 0;
            if (i < e) {
                const float4 p = pts[i];
                // cross = RN(RN(q0*px) + RN(q1*py)); 2*cross exact (self-add)
                const float cr = __fadd_rn(__fmul_rn(q0, p.x), __fmul_rn(q1, p.y));
                // v = RN(RN(qn + dn) - 2*cross)
                const float v  = __fsub_rn(__fadd_rn(qn, p.z), __fadd_rn(cr, cr));
                acc = (v <= r2);
                idx = __float_as_int(p.w);
            }
            const unsigned bal = __ballot_sync(gmask, acc);
            const unsigned nib = (bal >> shift) & 0xFu;
            if (acc) {
                const int s2 = cnt + __popc(nib & ((1u << sub) - 1u));
                if (s2 < CAP) cand[s2][qslot] = idx;
            }
            cnt += __popc(nib);
        }
    }

    float* out = nbr_idx + ((size_t)(b * NQ + oq)) * MAXN;
    const int k = cnt < CAP ? cnt : CAP;

    // -1 fill (slots k..63), split across the 4 lanes
    for (int s = k + sub; s < MAXN; s += LPQ) out[s] = -1.0f;

    // rank-selection emit: rank_i = #{j : v_j < v_i} is a permutation of
    // 0..k-1 (indices distinct) -> sorted output, scatter-order independent.
    for (int i = sub; i < k; i += LPQ) {
        const int v = cand[i][qslot];
        int rank = 0;
        #pragma unroll 4
        for (int j = 0; j < k; ++j)
            rank += (cand[j][qslot] < v) ? 1 : 0;
        out[rank] = (float)v;   // rank <= k-1 < MAXN <= CAP
    }

    if (sub == 0) g_counts[b * NQ + oq] = cnt;
}

// ---- row_splits (R6/R16 verbatim) ----
__global__ void __launch_bounds__(1024)
row_splits_kernel(float* __restrict__ row_splits)
{
    __shared__ int warp_sums[32];
    const int b = blockIdx.x;
    const int t = threadIdx.x;
    const int lane = t & 31, wid = t >> 5;

    const int* c = g_counts + b * NQ;
    const int base = t * 4;
    const int c0 = c[base + 0], c1 = c[base + 1], c2 = c[base + 2], c3 = c[base + 3];
    const int s0 = c0, s1 = s0 + c1, s2 = s1 + c2, s3 = s2 + c3;
    const int total = s3;

    int x = total;
    #pragma unroll
    for (int o = 1; o < 32; o <<= 1) {
        int y = __shfl_up_sync(0xFFFFFFFFu, x, o);
        if (lane >= o) x += y;
    }
    if (lane == 31) warp_sums[wid] = x;
    __syncthreads();
    if (wid == 0) {
        int w = warp_sums[lane];
        #pragma unroll
        for (int o = 1; o < 32; o <<= 1) {
            int y = __shfl_up_sync(0xFFFFFFFFu, w, o);
            if (lane >= o) w += y;
        }
        warp_sums[lane] = w;
    }
    __syncthreads();

    const int excl = (x - total) + (wid > 0 ? warp_sums[wid - 1] : 0);
    float* rs = row_splits + b * (NQ + 1);
    if (t == 0) rs[0] = 0.0f;
    rs[base + 1] = (float)(excl + s0);
    rs[base + 2] = (float)(excl + s1);
    rs[base + 3] = (float)(excl + s2);
    rs[base + 4] = (float)(excl + s3);
}

extern "C" void kernel_launch(void* const* d_in, const int* in_sizes, int n_in,
                              void* d_out, int out_size)
{
    const float* data    = (const float*)d_in[0];   // [8, 9225, 2]
    const float* queries = (const float*)d_in[1];   // [8, 4096, 2]
    const float* radius  = (const float*)d_in[2];   // scalar

    float* nbr_idx    = (float*)d_out;                          // [8, 4096, 64]
    float* row_splits = nbr_idx + (size_t)BATCH * NQ * MAXN;    // [8, 4097]

    bin_kernel<<<BATCH * PER_B, 1024>>>(data, queries);

    dim3 qgrid(NQ / QPB, BATCH);
    query_kernel<<<qgrid, QTPB>>>(radius, nbr_idx);
    row_splits_kernel<<<BATCH, 1024>>>(row_splits);
}